// round 7
// baseline (speedup 1.0000x reference)
#include <cuda_runtime.h>
#include <math.h>

#define NN 6000
#define NE 72000
#define PP 2
#define MM 9
#define FF 64
#define HH 4
#define CDIM 1664
#define NF 256
#define NPMF (NN*PP*MM*FF)

#define OFF_G1 0
#define OFF_B1 384
#define OFF_A1 448
#define OFF_G2 832
#define OFF_B2 1216
#define OFF_A2 1280

typedef unsigned long long u64;

__constant__ int c_deg[9] = {0,1,1,1,2,2,2,2,2};

// ---- scratch (static device globals; no runtime allocation) ----
__device__ float    g_c[NN*CDIM];
__device__ __align__(16) float g_xpre[NPMF];
__device__ __align__(16) float g_q[NPMF];
__device__ __align__(16) float g_k[NPMF];
__device__ __align__(16) float g_v[NPMF];
__device__ float    g_logits[NE*HH];
__device__ unsigned g_lmax[NN*HH];
__device__ float    g_w[NE*HH];
__device__ __align__(16) float g_denom[NN*HH];
__device__ __align__(8)  float2 g_sc2[NN];     // {sumcut, cnt}
__device__ __align__(16) float g_att[NPMF];
__device__ __align__(16) float g_x1[NPMF];
__device__ __align__(16) float g_xpre2[NPMF];
__device__ __align__(16) float g_gate[NN*NF];

__device__ __forceinline__ void fma2(u64 &d, u64 a, u64 b){
    asm("fma.rn.f32x2 %0, %1, %2, %0;" : "+l"(d) : "l"(a), "l"(b));
}
__device__ __forceinline__ float2 u2f2(u64 a){
    return make_float2(__uint_as_float((unsigned)a), __uint_as_float((unsigned)(a>>32)));
}
__device__ __forceinline__ unsigned flipf(float f){
    unsigned u = __float_as_uint(f);
    return (u & 0x80000000u) ? ~u : (u | 0x80000000u);
}
__device__ __forceinline__ float unflipf(unsigned u){
    return __uint_as_float((u & 0x80000000u) ? (u ^ 0x80000000u) : ~u);
}

// ---------------- time conditioning (+ folded init): LN(T) -> silu -> @W_c + b_c ----------------
__global__ void k_timecond(const float* __restrict__ ft, const float* __restrict__ scale,
                           const float* __restrict__ bias, const float* __restrict__ Wc,
                           const float* __restrict__ bc){
    __shared__ __align__(16) float2 sd[8*64];   // duplicated activations
    int n0 = blockIdx.x*8;
    int tid = threadIdx.x; // 256
    int gid = blockIdx.x*256 + tid;
    // folded init (750*256 = 192000 threads)
    {
        float4 z = make_float4(0.f,0.f,0.f,0.f);
        for (int i = gid; i < NPMF/4; i += 750*256) ((float4*)g_att)[i] = z;
        if (gid < NN*HH){ g_denom[gid] = 0.f; g_lmax[gid] = 0u; }
        if (gid < NN) g_sc2[gid] = make_float2(0.f, 0.f);
    }
    __shared__ __align__(16) float s[8][64];
    for (int i = tid; i < 512; i += 256){
        int nn = i>>6, f = i&63; int n = n0+nn;
        s[nn][f] = (n < NN) ? ft[n*64+f] : 0.f;
    }
    __syncthreads();
    int w = tid>>5, lane = tid&31;
    {
        float v0 = s[w][lane], v1 = s[w][lane+32];
        float sum = v0+v1, sq = v0*v0 + v1*v1;
        #pragma unroll
        for (int o = 16; o; o >>= 1){
            sum += __shfl_xor_sync(0xffffffffu, sum, o);
            sq  += __shfl_xor_sync(0xffffffffu, sq , o);
        }
        float mu = sum*(1.f/64.f);
        float var = sq*(1.f/64.f) - mu*mu;
        float rstd = rsqrtf(var + 1e-6f);
        float c0 = (v0-mu)*rstd*scale[lane]    + bias[lane];
        float c1 = (v1-mu)*rstd*scale[lane+32] + bias[lane+32];
        float y0 = c0 / (1.f + __expf(-c0));
        float y1 = c1 / (1.f + __expf(-c1));
        sd[w*64 + lane]      = make_float2(y0, y0);
        sd[w*64 + lane + 32] = make_float2(y1, y1);
    }
    __syncthreads();
    for (int jp = tid; jp < CDIM/2; jp += 256){
        int j0 = 2*jp;
        u64 acc[8];
        #pragma unroll
        for (int nn = 0; nn < 8; nn++) acc[nn] = 0ull;
        for (int t = 0; t < 64; t += 2){
            u64 w0 = *(const u64*)&Wc[(size_t)t*CDIM + j0];
            u64 w1 = *(const u64*)&Wc[(size_t)(t+1)*CDIM + j0];
            #pragma unroll
            for (int nn = 0; nn < 8; nn++){
                ulonglong2 x = *(const ulonglong2*)&sd[nn*64 + t];
                fma2(acc[nn], x.x, w0);
                fma2(acc[nn], x.y, w1);
            }
        }
        float2 bb = *(const float2*)&bc[j0];
        #pragma unroll
        for (int nn = 0; nn < 8; nn++){
            int n = n0+nn;
            if (n < NN){
                float2 r = u2f2(acc[nn]);
                *(float2*)&g_c[(size_t)n*CDIM + j0] = make_float2(r.x + bb.x, r.y + bb.y);
            }
        }
    }
}

// ---------------- equivariant LN + modulate ----------------
template<int PASS>
__global__ void k_ln_mod(const float* __restrict__ fn){
    int n = blockIdx.x;
    const float* xin  = PASS ? g_x1 : fn;
    float*       xout = PASS ? g_xpre2 : g_xpre;
    const int offG = PASS ? OFF_G2 : OFF_G1;
    const int offB = PASS ? OFF_B2 : OFF_B1;
    __shared__ float sm[1152];
    __shared__ float s_inv[2][3];
    __shared__ float s_mean[2];
    int tid = threadIdx.x; // 192
    for (int i = tid; i < 1152; i += 192) sm[i] = xin[(size_t)n*1152 + i];
    __syncthreads();
    int w = tid>>5, lane = tid&31;   // 6 warps = (p,l) pairs
    int p = w/3, l = w - 3*p;
    int base = p*576 + l*l*64;
    int cnt = (2*l+1)*64;
    float ss = 0.f, s1 = 0.f;
    for (int i = lane; i < cnt; i += 32){ float v = sm[base+i]; ss += v*v; s1 += v; }
    #pragma unroll
    for (int o = 16; o; o >>= 1){
        ss += __shfl_xor_sync(0xffffffffu, ss, o);
        s1 += __shfl_xor_sync(0xffffffffu, s1, o);
    }
    if (lane == 0){
        if (l == 0){ float mean = s1*(1.f/64.f); s_mean[p] = mean; ss -= 64.f*mean*mean; }
        s_inv[p][l] = rsqrtf(ss/(float)cnt + 1e-6f);
    }
    __syncthreads();
    const float* cc = g_c + (size_t)n*CDIM;
    for (int i = tid; i < 1152; i += 192){
        int p2 = i/576; int r = i - 576*p2; int m = r>>6; int f = r&63;
        int l2 = c_deg[m];
        float v = sm[i];
        if (m == 0) v -= s_mean[p2];
        float gmod = cc[offG + (p2*3+l2)*64 + f];
        float y = v * s_inv[p2][l2] * (1.f + gmod);
        if (m == 0) y += cc[offB + f];
        xout[(size_t)n*1152 + i] = y;
    }
}

// ---------------- QKV projections: 32 nodes/block, g-pair f32x2 ----------------
__global__ void __launch_bounds__(256) k_qkv(const float* __restrict__ Wq, const float* __restrict__ Wk,
                      const float* __restrict__ Wv){
    int n0 = blockIdx.x*32;
    int pm = blockIdx.y; int p = pm/9, m = pm - 9*p; int l = c_deg[m];
    __shared__ __align__(16) float2 xs[32*64];   // duplicated, 16 KB
    int tid = threadIdx.x; // 256
    for (int i = tid; i < 2048; i += 256){
        int nn = i>>6, f = i&63; int n = n0+nn;
        float v = (n < NN) ? g_xpre[((size_t)(n*PP+p)*MM+m)*FF + f] : 0.f;
        xs[i] = make_float2(v, v);
    }
    __syncthreads();
    int gp = tid&31, ng = tid>>5;   // 32 g-pairs x 8 node-groups(4 nodes)
    int g0 = 2*gp;
    const float* wq = Wq + (size_t)(p*3+l)*4096 + g0;
    const float* wk = Wk + (size_t)(p*3+l)*4096 + g0;
    const float* wv = Wv + (size_t)(p*3+l)*4096 + g0;
    u64 aq[4], ak[4], av[4];
    #pragma unroll
    for (int j = 0; j < 4; j++){ aq[j]=0ull; ak[j]=0ull; av[j]=0ull; }
    for (int f = 0; f < 64; f += 2){
        u64 q0 = *(const u64*)&wq[f*64],     k0 = *(const u64*)&wk[f*64],     v0 = *(const u64*)&wv[f*64];
        u64 q1 = *(const u64*)&wq[(f+1)*64], k1 = *(const u64*)&wk[(f+1)*64], v1 = *(const u64*)&wv[(f+1)*64];
        #pragma unroll
        for (int j = 0; j < 4; j++){
            ulonglong2 x = *(const ulonglong2*)&xs[(ng*4+j)*64 + f];
            fma2(aq[j], x.x, q0); fma2(aq[j], x.y, q1);
            fma2(ak[j], x.x, k0); fma2(ak[j], x.y, k1);
            fma2(av[j], x.x, v0); fma2(av[j], x.y, v1);
        }
    }
    #pragma unroll
    for (int j = 0; j < 4; j++){
        int n = n0 + ng*4 + j;
        if (n < NN){
            int idx = ((n*PP+p)*MM+m)*FF + g0;
            *(float2*)&g_q[idx] = u2f2(aq[j]);
            *(float2*)&g_k[idx] = u2f2(ak[j]);
            *(float2*)&g_v[idx] = u2f2(av[j]);
        }
    }
}

// ---------------- per-edge: e_qk projection + logits + segment max (4 edges/block) ----------------
__global__ void __launch_bounds__(128) k_logits(const float* __restrict__ fe, const float* __restrict__ Weqk,
                         const int* __restrict__ src, const int* __restrict__ dst){
    int e0 = blockIdx.x*4;
    __shared__ __align__(16) float2 sfd[4*576];   // duplicated fe, 18 KB
    __shared__ __align__(16) float seqk[4*576];   // 9 KB
    int tid = threadIdx.x; // 128
    const float4* fp = (const float4*)(fe + (size_t)e0*576);
    for (int i = tid; i < 576; i += 128){
        float4 v = fp[i];
        int b = i*4;
        sfd[b+0] = make_float2(v.x, v.x);
        sfd[b+1] = make_float2(v.y, v.y);
        sfd[b+2] = make_float2(v.z, v.z);
        sfd[b+3] = make_float2(v.w, v.w);
    }
    __syncthreads();
    {
        int gp = tid&31, e = tid>>5;   // warp = one edge
        int g0 = 2*gp;
        const float* wt = Weqk + g0;
        u64 acc[9];
        #pragma unroll
        for (int m = 0; m < 9; m++) acc[m] = 0ull;
        for (int f = 0; f < 64; f += 2){
            u64 w0 = *(const u64*)&wt[f*64];
            u64 w1 = *(const u64*)&wt[(f+1)*64];
            #pragma unroll
            for (int m = 0; m < 9; m++){
                ulonglong2 x = *(const ulonglong2*)&sfd[e*576 + m*64 + f];
                fma2(acc[m], x.x, w0); fma2(acc[m], x.y, w1);
            }
        }
        #pragma unroll
        for (int m = 0; m < 9; m++)
            *(float2*)&seqk[e*576 + m*64 + g0] = u2f2(acc[m]);
    }
    __syncthreads();
    int h = tid>>5, lane = tid&31;
    int f = h*16 + (lane&15);
    #pragma unroll
    for (int e = 0; e < 4; e++){
        int s = src[e0+e], d = dst[e0+e];
        float acc = 0.f;
        for (int pm = (lane>>4); pm < 18; pm += 2){
            int p = pm/9, m = pm - 9*p;
            int off = ((p)*MM+m)*FF + f;
            acc += g_q[(size_t)d*1152 + off] * g_k[(size_t)s*1152 + off] * seqk[e*576 + m*64+f];
        }
        #pragma unroll
        for (int o = 16; o; o >>= 1) acc += __shfl_xor_sync(0xffffffffu, acc, o);
        if (lane == 0){
            float lg = acc * 0.05892556509887896f;  // 1/sqrt(288)
            g_logits[(e0+e)*HH + h] = lg;
            atomicMax(&g_lmax[d*HH + h], flipf(lg));
        }
    }
}

// ---------------- softmax weights + segment sums (vectorized reds) ----------------
__global__ void k_softmax_w(const int* __restrict__ dst, const float* __restrict__ cutoff){
    int e = blockIdx.x*256 + threadIdx.x;
    if (e >= NE) return;
    int d = dst[e];
    float cut = cutoff[e];
    float wv[HH];
    #pragma unroll
    for (int h = 0; h < HH; h++){
        float lg = g_logits[e*HH + h];
        float lm = unflipf(g_lmax[d*HH + h]);
        wv[h] = __expf(lg - lm) * cut;
        g_w[e*HH + h] = wv[h];
    }
    asm volatile("red.global.add.v4.f32 [%0], {%1,%2,%3,%4};"
                 :: "l"(&g_denom[d*HH]), "f"(wv[0]), "f"(wv[1]), "f"(wv[2]), "f"(wv[3])
                 : "memory");
    asm volatile("red.global.add.v2.f32 [%0], {%1,%2};"
                 :: "l"(&g_sc2[d]), "f"(cut), "f"(1.0f) : "memory");
}

// ---------------- per-edge: e_v projection + attn*v scatter (4 edges/block, v4 red) ----------------
__global__ void __launch_bounds__(128) k_scatter(const float* __restrict__ fe, const float* __restrict__ Wev,
                          const int* __restrict__ src, const int* __restrict__ dst){
    int e0 = blockIdx.x*4;
    __shared__ __align__(16) float2 sfd[4*576];   // 18 KB
    __shared__ __align__(16) float sev[4*576];    // 9 KB
    __shared__ float satt[4][4];
    int tid = threadIdx.x; // 128
    const float4* fp = (const float4*)(fe + (size_t)e0*576);
    for (int i = tid; i < 576; i += 128){
        float4 v = fp[i];
        int b = i*4;
        sfd[b+0] = make_float2(v.x, v.x);
        sfd[b+1] = make_float2(v.y, v.y);
        sfd[b+2] = make_float2(v.z, v.z);
        sfd[b+3] = make_float2(v.w, v.w);
    }
    if (tid < 16){
        int e = tid>>2, h = tid&3;
        int d = dst[e0+e];
        satt[e][h] = g_w[(e0+e)*HH + h] / (g_denom[d*HH + h] + 1e-9f);
    }
    __syncthreads();
    {
        int gp = tid&31, e = tid>>5;
        int g0 = 2*gp;
        const float* wt = Wev + g0;
        u64 acc[9];
        #pragma unroll
        for (int m = 0; m < 9; m++) acc[m] = 0ull;
        for (int f = 0; f < 64; f += 2){
            u64 w0 = *(const u64*)&wt[f*64];
            u64 w1 = *(const u64*)&wt[(f+1)*64];
            #pragma unroll
            for (int m = 0; m < 9; m++){
                ulonglong2 x = *(const ulonglong2*)&sfd[e*576 + m*64 + f];
                fma2(acc[m], x.x, w0); fma2(acc[m], x.y, w1);
            }
        }
        #pragma unroll
        for (int m = 0; m < 9; m++)
            *(float2*)&sev[e*576 + m*64 + g0] = u2f2(acc[m]);
    }
    __syncthreads();
    #pragma unroll
    for (int e = 0; e < 4; e++){
        int d = dst[e0+e], s = src[e0+e];
        for (int i4 = tid; i4 < 288; i4 += 128){
            int i = i4*4;
            int p = i/576; int r = i - 576*p; int m = r>>6; int f = r&63; int h = f>>4;
            float4 vv = *(const float4*)&g_v[((size_t)(s*PP+p)*MM+m)*FF + f];
            float4 ev = *(const float4*)&sev[e*576 + m*64+f];
            float a = satt[e][h];
            float* op = &g_att[((size_t)(d*PP+p)*MM+m)*FF + f];
            float r0 = a*vv.x*ev.x, r1 = a*vv.y*ev.y, r2 = a*vv.z*ev.z, r3 = a*vv.w*ev.w;
            asm volatile("red.global.add.v4.f32 [%0], {%1,%2,%3,%4};"
                         :: "l"(op), "f"(r0), "f"(r1), "f"(r2), "f"(r3) : "memory");
        }
    }
}

// ---------------- Wo projection + mean_cut select + residual 1 (32 nodes/block, f32x2) ----------------
__global__ void __launch_bounds__(256) k_out_res(const float* __restrict__ fn, const float* __restrict__ Wo){
    int n0 = blockIdx.x*32;
    int pm = blockIdx.y; int p = pm/9, m = pm - 9*p; int l = c_deg[m];
    __shared__ __align__(16) float2 xs[32*64];   // 16 KB
    int tid = threadIdx.x; // 256
    for (int i = tid; i < 2048; i += 256){
        int nn = i>>6, f = i&63; int n = n0+nn;
        float v = (n < NN) ? g_att[((size_t)(n*PP+p)*MM+m)*FF + f] : 0.f;
        xs[i] = make_float2(v, v);
    }
    __syncthreads();
    int gp = tid&31, ng = tid>>5;
    int g0 = 2*gp;
    const float* wo = Wo + (size_t)(p*3+l)*4096 + g0;
    u64 acc[4];
    #pragma unroll
    for (int j = 0; j < 4; j++) acc[j] = 0ull;
    for (int f = 0; f < 64; f += 2){
        u64 w0 = *(const u64*)&wo[f*64];
        u64 w1 = *(const u64*)&wo[(f+1)*64];
        #pragma unroll
        for (int j = 0; j < 4; j++){
            ulonglong2 x = *(const ulonglong2*)&xs[(ng*4+j)*64 + f];
            fma2(acc[j], x.x, w0); fma2(acc[j], x.y, w1);
        }
    }
    #pragma unroll
    for (int j = 0; j < 4; j++){
        int n = n0 + ng*4 + j;
        if (n < NN){
            float2 sc = g_sc2[n];
            float mc = sc.x / fmaxf(sc.y, 1.f);
            int idx = ((n*PP+p)*MM+m)*FF + g0;
            float2 o = u2f2(acc[j]);
            float2 xp = *(const float2*)&g_xpre[idx];
            if (mc < 1e-5f) o = xp;
            float2 a1 = *(const float2*)&g_c[(size_t)n*CDIM + OFF_A1 + (p*3+l)*64 + g0];
            float2 fv = *(const float2*)&fn[idx];
            *(float2*)&g_x1[idx] = make_float2(fv.x + a1.x*o.x, fv.y + a1.y*o.y);
        }
    }
}

// ---------------- gelu-ratio gate from h[:,0,0,:] ----------------
__global__ void k_gate(const float* __restrict__ W1){
    int n = blockIdx.x;
    __shared__ __align__(16) float xs[64];
    int tid = threadIdx.x; // 256
    if (tid < 64) xs[tid] = g_xpre2[(size_t)n*1152 + tid];
    __syncthreads();
    float acc = 0.f;
    for (int f = 0; f < 64; f += 4){
        float4 x = *(const float4*)&xs[f];
        acc += x.x*W1[f*256+tid] + x.y*W1[(f+1)*256+tid]
             + x.z*W1[(f+2)*256+tid] + x.w*W1[(f+3)*256+tid];
    }
    float s = acc;
    float t = tanhf(0.7978845608028654f*(s + 0.044715f*s*s*s));
    g_gate[(size_t)n*NF + tid] = 0.5f*(1.f + t);
}

// ---------------- fused MLP: 16 nodes/block, f32x2 both phases ----------------
__global__ void __launch_bounds__(256) k_mlp(const float* __restrict__ W1, const float* __restrict__ W2,
                      float* __restrict__ out){
    int n0 = blockIdx.x*16;
    int pm = blockIdx.y; int p = pm/9, m = pm - 9*p; int l = c_deg[m];
    __shared__ __align__(16) float2 xs[16*64];    // 8 KB dup
    __shared__ __align__(16) float2 hs[16*256];   // 32 KB dup
    int tid = threadIdx.x; // 256
    for (int i = tid; i < 1024; i += 256){
        int nn = i>>6, f = i&63; int n = n0+nn;
        float v = (n < NN) ? g_xpre2[((size_t)(n*PP+p)*MM+m)*FF + f] : 0.f;
        xs[i] = make_float2(v, v);
    }
    __syncthreads();
    // phase 1: h = (X @ W1) * gate ; 128 j-pairs x 2 node-groups(8)
    {
        int jp = tid&127, ng = tid>>7;
        int j0 = 2*jp;
        const float* w1 = W1 + (size_t)(p*3+l)*64*256 + j0;
        u64 acc[8];
        #pragma unroll
        for (int nn = 0; nn < 8; nn++) acc[nn] = 0ull;
        for (int f = 0; f < 64; f += 2){
            u64 w0 = *(const u64*)&w1[f*256];
            u64 w1v = *(const u64*)&w1[(f+1)*256];
            #pragma unroll
            for (int nn = 0; nn < 8; nn++){
                ulonglong2 x = *(const ulonglong2*)&xs[(ng*8+nn)*64 + f];
                fma2(acc[nn], x.x, w0); fma2(acc[nn], x.y, w1v);
            }
        }
        #pragma unroll
        for (int nn = 0; nn < 8; nn++){
            int node = ng*8+nn;
            int n = n0 + node;
            float2 gt = (n < NN) ? *(const float2*)&g_gate[(size_t)n*NF + j0] : make_float2(0.f,0.f);
            float2 h = u2f2(acc[nn]);
            float h0 = h.x*gt.x, h1 = h.y*gt.y;
            hs[node*256 + j0]     = make_float2(h0, h0);
            hs[node*256 + j0 + 1] = make_float2(h1, h1);
        }
    }
    __syncthreads();
    // phase 2: out = gate(a2, h @ W2) + x1 ; 32 g-pairs x 8 node-groups(2)
    {
        int gp = tid&31, ng = tid>>5;
        int g0 = 2*gp;
        const float* w2 = W2 + (size_t)(p*3+l)*256*64 + g0;
        u64 acc[2] = {0ull, 0ull};
        for (int jj = 0; jj < 256; jj += 2){
            u64 w0 = *(const u64*)&w2[jj*64];
            u64 w1v = *(const u64*)&w2[(jj+1)*64];
            #pragma unroll
            for (int k2 = 0; k2 < 2; k2++){
                ulonglong2 h = *(const ulonglong2*)&hs[(ng*2+k2)*256 + jj];
                fma2(acc[k2], h.x, w0); fma2(acc[k2], h.y, w1v);
            }
        }
        #pragma unroll
        for (int k2 = 0; k2 < 2; k2++){
            int n = n0 + ng*2 + k2;
            if (n < NN){
                int idx = ((n*PP+p)*MM+m)*FF + g0;
                float2 a2 = *(const float2*)&g_c[(size_t)n*CDIM + OFF_A2 + (p*3+l)*64 + g0];
                float2 r = u2f2(acc[k2]);
                float2 x1 = *(const float2*)&g_x1[idx];
                *(float2*)&out[idx] = make_float2(x1.x + a2.x*r.x, x1.y + a2.y*r.y);
            }
        }
    }
}

extern "C" void kernel_launch(void* const* d_in, const int* in_sizes, int n_in,
                              void* d_out, int out_size){
    const float* fn    = (const float*)d_in[0];
    const float* fe    = (const float*)d_in[1];
    const float* ft    = (const float*)d_in[2];
    const float* cut   = (const float*)d_in[3];
    const float* lns   = (const float*)d_in[4];
    const float* lnb   = (const float*)d_in[5];
    const float* Wc    = (const float*)d_in[6];
    const float* bc    = (const float*)d_in[7];
    const float* Wq    = (const float*)d_in[8];
    const float* Wk    = (const float*)d_in[9];
    const float* Wv    = (const float*)d_in[10];
    const float* Wo    = (const float*)d_in[11];
    const float* Weqk  = (const float*)d_in[12];
    const float* Wev   = (const float*)d_in[13];
    const float* W1    = (const float*)d_in[14];
    const float* W2    = (const float*)d_in[15];
    const int*   src   = (const int*)d_in[16];
    const int*   dst   = (const int*)d_in[17];
    float* out = (float*)d_out;

    k_timecond<<<NN/8, 256>>>(ft, lns, lnb, Wc, bc);   // includes init
    k_ln_mod<0><<<NN, 192>>>(fn);
    dim3 gpm((NN+31)/32, PP*MM);
    k_qkv<<<gpm, 256>>>(Wq, Wk, Wv);
    k_logits<<<NE/4, 128>>>(fe, Weqk, src, dst);       // launch #4 -> profiled
    k_softmax_w<<<(NE+255)/256, 256>>>(dst, cut);
    k_scatter<<<NE/4, 128>>>(fe, Wev, src, dst);
    k_out_res<<<gpm, 256>>>(fn, Wo);
    k_ln_mod<1><<<NN, 192>>>(fn);
    k_gate<<<NN, 256>>>(W1);
    dim3 gpm16((NN+15)/16, PP*MM);
    k_mlp<<<gpm16, 256>>>(W1, W2, out);
}

// round 8
// speedup vs baseline: 1.0303x; 1.0303x over previous
#include <cuda_runtime.h>
#include <math.h>

#define NN 6000
#define NE 72000
#define PP 2
#define MM 9
#define FF 64
#define HH 4
#define CDIM 1664
#define NF 256
#define NPMF (NN*PP*MM*FF)

#define OFF_G1 0
#define OFF_B1 384
#define OFF_A1 448
#define OFF_G2 832
#define OFF_B2 1216
#define OFF_A2 1280

typedef unsigned long long u64;

__constant__ int c_deg[9] = {0,1,1,1,2,2,2,2,2};

// ---- scratch (static device globals; no runtime allocation) ----
__device__ float    g_c[NN*CDIM];
__device__ __align__(16) float g_xpre[NPMF];
__device__ __align__(16) float g_q[NPMF];
__device__ __align__(16) float g_k[NPMF];
__device__ __align__(16) float g_v[NPMF];
__device__ float    g_logits[NE*HH];
__device__ unsigned g_lmax[NN*HH];
__device__ float    g_w[NE*HH];
__device__ __align__(16) float g_denom[NN*HH];
__device__ __align__(8)  float2 g_sc2[NN];     // {sumcut, cnt}
__device__ __align__(16) float g_att[NPMF];
__device__ __align__(16) float g_x1[NPMF];
__device__ __align__(16) float g_xpre2[NPMF];
__device__ __align__(16) float g_gate[NN*NF];

__device__ __forceinline__ void fma2(u64 &d, u64 a, u64 b){
    asm("fma.rn.f32x2 %0, %1, %2, %0;" : "+l"(d) : "l"(a), "l"(b));
}
__device__ __forceinline__ float2 u2f2(u64 a){
    return make_float2(__uint_as_float((unsigned)a), __uint_as_float((unsigned)(a>>32)));
}
__device__ __forceinline__ unsigned flipf(float f){
    unsigned u = __float_as_uint(f);
    return (u & 0x80000000u) ? ~u : (u | 0x80000000u);
}
__device__ __forceinline__ float unflipf(unsigned u){
    return __uint_as_float((u & 0x80000000u) ? (u ^ 0x80000000u) : ~u);
}

// ---------------- time conditioning (+ folded init): LN(T) -> silu -> @W_c + b_c ----------------
__global__ void k_timecond(const float* __restrict__ ft, const float* __restrict__ scale,
                           const float* __restrict__ bias, const float* __restrict__ Wc,
                           const float* __restrict__ bc){
    __shared__ __align__(16) float2 sd[8*64];   // duplicated activations
    int n0 = blockIdx.x*8;
    int tid = threadIdx.x; // 256
    int gid = blockIdx.x*256 + tid;
    // folded init
    {
        float4 z = make_float4(0.f,0.f,0.f,0.f);
        for (int i = gid; i < NPMF/4; i += 750*256) ((float4*)g_att)[i] = z;
        if (gid < NN*HH){ g_denom[gid] = 0.f; g_lmax[gid] = 0u; }
        if (gid < NN) g_sc2[gid] = make_float2(0.f, 0.f);
    }
    __shared__ __align__(16) float s[8][64];
    for (int i = tid; i < 512; i += 256){
        int nn = i>>6, f = i&63; int n = n0+nn;
        s[nn][f] = (n < NN) ? ft[n*64+f] : 0.f;
    }
    __syncthreads();
    int w = tid>>5, lane = tid&31;
    {
        float v0 = s[w][lane], v1 = s[w][lane+32];
        float sum = v0+v1, sq = v0*v0 + v1*v1;
        #pragma unroll
        for (int o = 16; o; o >>= 1){
            sum += __shfl_xor_sync(0xffffffffu, sum, o);
            sq  += __shfl_xor_sync(0xffffffffu, sq , o);
        }
        float mu = sum*(1.f/64.f);
        float var = sq*(1.f/64.f) - mu*mu;
        float rstd = rsqrtf(var + 1e-6f);
        float c0 = (v0-mu)*rstd*scale[lane]    + bias[lane];
        float c1 = (v1-mu)*rstd*scale[lane+32] + bias[lane+32];
        float y0 = c0 / (1.f + __expf(-c0));
        float y1 = c1 / (1.f + __expf(-c1));
        sd[w*64 + lane]      = make_float2(y0, y0);
        sd[w*64 + lane + 32] = make_float2(y1, y1);
    }
    __syncthreads();
    for (int jp = tid; jp < CDIM/2; jp += 256){
        int j0 = 2*jp;
        u64 acc[8];
        #pragma unroll
        for (int nn = 0; nn < 8; nn++) acc[nn] = 0ull;
        for (int t = 0; t < 64; t += 2){
            u64 w0 = *(const u64*)&Wc[(size_t)t*CDIM + j0];
            u64 w1 = *(const u64*)&Wc[(size_t)(t+1)*CDIM + j0];
            #pragma unroll
            for (int nn = 0; nn < 8; nn++){
                ulonglong2 x = *(const ulonglong2*)&sd[nn*64 + t];
                fma2(acc[nn], x.x, w0);
                fma2(acc[nn], x.y, w1);
            }
        }
        float2 bb = *(const float2*)&bc[j0];
        #pragma unroll
        for (int nn = 0; nn < 8; nn++){
            int n = n0+nn;
            if (n < NN){
                float2 r = u2f2(acc[nn]);
                *(float2*)&g_c[(size_t)n*CDIM + j0] = make_float2(r.x + bb.x, r.y + bb.y);
            }
        }
    }
}

// ---------------- equivariant LN + modulate ----------------
template<int PASS>
__global__ void k_ln_mod(const float* __restrict__ fn){
    int n = blockIdx.x;
    const float* xin  = PASS ? g_x1 : fn;
    float*       xout = PASS ? g_xpre2 : g_xpre;
    const int offG = PASS ? OFF_G2 : OFF_G1;
    const int offB = PASS ? OFF_B2 : OFF_B1;
    __shared__ float sm[1152];
    __shared__ float s_inv[2][3];
    __shared__ float s_mean[2];
    int tid = threadIdx.x; // 192
    for (int i = tid; i < 1152; i += 192) sm[i] = xin[(size_t)n*1152 + i];
    __syncthreads();
    int w = tid>>5, lane = tid&31;   // 6 warps = (p,l) pairs
    int p = w/3, l = w - 3*p;
    int base = p*576 + l*l*64;
    int cnt = (2*l+1)*64;
    float ss = 0.f, s1 = 0.f;
    for (int i = lane; i < cnt; i += 32){ float v = sm[base+i]; ss += v*v; s1 += v; }
    #pragma unroll
    for (int o = 16; o; o >>= 1){
        ss += __shfl_xor_sync(0xffffffffu, ss, o);
        s1 += __shfl_xor_sync(0xffffffffu, s1, o);
    }
    if (lane == 0){
        if (l == 0){ float mean = s1*(1.f/64.f); s_mean[p] = mean; ss -= 64.f*mean*mean; }
        s_inv[p][l] = rsqrtf(ss/(float)cnt + 1e-6f);
    }
    __syncthreads();
    const float* cc = g_c + (size_t)n*CDIM;
    for (int i = tid; i < 1152; i += 192){
        int p2 = i/576; int r = i - 576*p2; int m = r>>6; int f = r&63;
        int l2 = c_deg[m];
        float v = sm[i];
        if (m == 0) v -= s_mean[p2];
        float gmod = cc[offG + (p2*3+l2)*64 + f];
        float y = v * s_inv[p2][l2] * (1.f + gmod);
        if (m == 0) y += cc[offB + f];
        xout[(size_t)n*1152 + i] = y;
    }
}

// ---------------- QKV projections: 32 nodes/block, g-pair f32x2 ----------------
__global__ void __launch_bounds__(256) k_qkv(const float* __restrict__ Wq, const float* __restrict__ Wk,
                      const float* __restrict__ Wv){
    int n0 = blockIdx.x*32;
    int pm = blockIdx.y; int p = pm/9, m = pm - 9*p; int l = c_deg[m];
    __shared__ __align__(16) float2 xs[32*64];   // duplicated, 16 KB
    int tid = threadIdx.x; // 256
    for (int i = tid; i < 2048; i += 256){
        int nn = i>>6, f = i&63; int n = n0+nn;
        float v = (n < NN) ? g_xpre[((size_t)(n*PP+p)*MM+m)*FF + f] : 0.f;
        xs[i] = make_float2(v, v);
    }
    __syncthreads();
    int gp = tid&31, ng = tid>>5;   // 32 g-pairs x 8 node-groups(4 nodes)
    int g0 = 2*gp;
    const float* wq = Wq + (size_t)(p*3+l)*4096 + g0;
    const float* wk = Wk + (size_t)(p*3+l)*4096 + g0;
    const float* wv = Wv + (size_t)(p*3+l)*4096 + g0;
    u64 aq[4], ak[4], av[4];
    #pragma unroll
    for (int j = 0; j < 4; j++){ aq[j]=0ull; ak[j]=0ull; av[j]=0ull; }
    for (int f = 0; f < 64; f += 2){
        u64 q0 = *(const u64*)&wq[f*64],     k0 = *(const u64*)&wk[f*64],     v0 = *(const u64*)&wv[f*64];
        u64 q1 = *(const u64*)&wq[(f+1)*64], k1 = *(const u64*)&wk[(f+1)*64], v1 = *(const u64*)&wv[(f+1)*64];
        #pragma unroll
        for (int j = 0; j < 4; j++){
            ulonglong2 x = *(const ulonglong2*)&xs[(ng*4+j)*64 + f];
            fma2(aq[j], x.x, q0); fma2(aq[j], x.y, q1);
            fma2(ak[j], x.x, k0); fma2(ak[j], x.y, k1);
            fma2(av[j], x.x, v0); fma2(av[j], x.y, v1);
        }
    }
    #pragma unroll
    for (int j = 0; j < 4; j++){
        int n = n0 + ng*4 + j;
        if (n < NN){
            int idx = ((n*PP+p)*MM+m)*FF + g0;
            *(float2*)&g_q[idx] = u2f2(aq[j]);
            *(float2*)&g_k[idx] = u2f2(ak[j]);
            *(float2*)&g_v[idx] = u2f2(av[j]);
        }
    }
}

// ---------------- per-edge: e_qk projection + logits + segment max (4 edges/block) ----------------
__global__ void __launch_bounds__(128) k_logits(const float* __restrict__ fe, const float* __restrict__ Weqk,
                         const int* __restrict__ src, const int* __restrict__ dst){
    int e0 = blockIdx.x*4;
    __shared__ __align__(16) float2 sfd[4*576];   // duplicated fe, 18 KB
    __shared__ __align__(16) float seqk[4*576];   // 9 KB
    int tid = threadIdx.x; // 128
    const float4* fp = (const float4*)(fe + (size_t)e0*576);
    for (int i = tid; i < 576; i += 128){
        float4 v = fp[i];
        int b = i*4;
        *(float4*)&sfd[b]   = make_float4(v.x, v.x, v.y, v.y);
        *(float4*)&sfd[b+2] = make_float4(v.z, v.z, v.w, v.w);
    }
    __syncthreads();
    {
        int gp = tid&31, e = tid>>5;   // warp = one edge
        int g0 = 2*gp;
        const float* wt = Weqk + g0;
        u64 acc[9];
        #pragma unroll
        for (int m = 0; m < 9; m++) acc[m] = 0ull;
        for (int f = 0; f < 64; f += 2){
            u64 w0 = *(const u64*)&wt[f*64];
            u64 w1 = *(const u64*)&wt[(f+1)*64];
            #pragma unroll
            for (int m = 0; m < 9; m++){
                ulonglong2 x = *(const ulonglong2*)&sfd[e*576 + m*64 + f];
                fma2(acc[m], x.x, w0); fma2(acc[m], x.y, w1);
            }
        }
        #pragma unroll
        for (int m = 0; m < 9; m++)
            *(float2*)&seqk[e*576 + m*64 + g0] = u2f2(acc[m]);
    }
    __syncthreads();
    // dot phase: warp = edge, lane = (h, i) ; 2 f per lane per pm step
    {
        int we = tid>>5, lane = tid&31;
        int h = lane>>3, i = lane&7;
        int s = src[e0+we], d = dst[e0+we];
        int f0 = h*16 + 2*i;
        const float* qb = g_q + (size_t)d*1152 + f0;
        const float* kb = g_k + (size_t)s*1152 + f0;
        const float* sb = seqk + we*576 + f0;
        float acc = 0.f;
        #pragma unroll
        for (int pm = 0; pm < 18; pm++){
            int moff = (pm >= 9 ? pm-9 : pm)*64;
            float2 q2 = *(const float2*)&qb[pm*64];
            float2 k2 = *(const float2*)&kb[pm*64];
            float2 s2 = *(const float2*)&sb[moff];
            acc += q2.x*k2.x*s2.x + q2.y*k2.y*s2.y;
        }
        acc += __shfl_xor_sync(0xffffffffu, acc, 1);
        acc += __shfl_xor_sync(0xffffffffu, acc, 2);
        acc += __shfl_xor_sync(0xffffffffu, acc, 4);
        if (i == 0){
            float lg = acc * 0.05892556509887896f;  // 1/sqrt(288)
            g_logits[(e0+we)*HH + h] = lg;
            atomicMax(&g_lmax[d*HH + h], flipf(lg));
        }
    }
}

// ---------------- softmax weights + segment sums (vectorized reds) ----------------
__global__ void k_softmax_w(const int* __restrict__ dst, const float* __restrict__ cutoff){
    int e = blockIdx.x*256 + threadIdx.x;
    if (e >= NE) return;
    int d = dst[e];
    float cut = cutoff[e];
    float wv[HH];
    #pragma unroll
    for (int h = 0; h < HH; h++){
        float lg = g_logits[e*HH + h];
        float lm = unflipf(g_lmax[d*HH + h]);
        wv[h] = __expf(lg - lm) * cut;
        g_w[e*HH + h] = wv[h];
    }
    asm volatile("red.global.add.v4.f32 [%0], {%1,%2,%3,%4};"
                 :: "l"(&g_denom[d*HH]), "f"(wv[0]), "f"(wv[1]), "f"(wv[2]), "f"(wv[3])
                 : "memory");
    asm volatile("red.global.add.v2.f32 [%0], {%1,%2};"
                 :: "l"(&g_sc2[d]), "f"(cut), "f"(1.0f) : "memory");
}

// ---------------- per-edge: e_v projection + attn*v scatter (4 edges/block, v4 red) ----------------
__global__ void __launch_bounds__(128) k_scatter(const float* __restrict__ fe, const float* __restrict__ Wev,
                          const int* __restrict__ src, const int* __restrict__ dst){
    int e0 = blockIdx.x*4;
    __shared__ __align__(16) float2 sfd[4*576];   // 18 KB
    __shared__ __align__(16) float sev[4*576];    // 9 KB
    __shared__ float satt[4][4];
    int tid = threadIdx.x; // 128
    const float4* fp = (const float4*)(fe + (size_t)e0*576);
    for (int i = tid; i < 576; i += 128){
        float4 v = fp[i];
        int b = i*4;
        *(float4*)&sfd[b]   = make_float4(v.x, v.x, v.y, v.y);
        *(float4*)&sfd[b+2] = make_float4(v.z, v.z, v.w, v.w);
    }
    if (tid < 16){
        int e = tid>>2, h = tid&3;
        int d = dst[e0+e];
        satt[e][h] = g_w[(e0+e)*HH + h] / (g_denom[d*HH + h] + 1e-9f);
    }
    __syncthreads();
    {
        int gp = tid&31, e = tid>>5;
        int g0 = 2*gp;
        const float* wt = Wev + g0;
        u64 acc[9];
        #pragma unroll
        for (int m = 0; m < 9; m++) acc[m] = 0ull;
        for (int f = 0; f < 64; f += 2){
            u64 w0 = *(const u64*)&wt[f*64];
            u64 w1 = *(const u64*)&wt[(f+1)*64];
            #pragma unroll
            for (int m = 0; m < 9; m++){
                ulonglong2 x = *(const ulonglong2*)&sfd[e*576 + m*64 + f];
                fma2(acc[m], x.x, w0); fma2(acc[m], x.y, w1);
            }
        }
        #pragma unroll
        for (int m = 0; m < 9; m++)
            *(float2*)&sev[e*576 + m*64 + g0] = u2f2(acc[m]);
    }
    __syncthreads();
    #pragma unroll
    for (int e = 0; e < 4; e++){
        int d = dst[e0+e], s = src[e0+e];
        for (int i4 = tid; i4 < 288; i4 += 128){
            int i = i4*4;
            int p = i/576; int r = i - 576*p; int m = r>>6; int f = r&63; int h = f>>4;
            float4 vv = *(const float4*)&g_v[((size_t)(s*PP+p)*MM+m)*FF + f];
            float4 ev = *(const float4*)&sev[e*576 + m*64+f];
            float a = satt[e][h];
            float* op = &g_att[((size_t)(d*PP+p)*MM+m)*FF + f];
            float r0 = a*vv.x*ev.x, r1 = a*vv.y*ev.y, r2 = a*vv.z*ev.z, r3 = a*vv.w*ev.w;
            asm volatile("red.global.add.v4.f32 [%0], {%1,%2,%3,%4};"
                         :: "l"(op), "f"(r0), "f"(r1), "f"(r2), "f"(r3) : "memory");
        }
    }
}

// ---------------- Wo projection + mean_cut select + residual 1 (32 nodes/block, f32x2) ----------------
__global__ void __launch_bounds__(256) k_out_res(const float* __restrict__ fn, const float* __restrict__ Wo){
    int n0 = blockIdx.x*32;
    int pm = blockIdx.y; int p = pm/9, m = pm - 9*p; int l = c_deg[m];
    __shared__ __align__(16) float2 xs[32*64];   // 16 KB
    int tid = threadIdx.x; // 256
    for (int i = tid; i < 2048; i += 256){
        int nn = i>>6, f = i&63; int n = n0+nn;
        float v = (n < NN) ? g_att[((size_t)(n*PP+p)*MM+m)*FF + f] : 0.f;
        xs[i] = make_float2(v, v);
    }
    __syncthreads();
    int gp = tid&31, ng = tid>>5;
    int g0 = 2*gp;
    const float* wo = Wo + (size_t)(p*3+l)*4096 + g0;
    u64 acc[4];
    #pragma unroll
    for (int j = 0; j < 4; j++) acc[j] = 0ull;
    for (int f = 0; f < 64; f += 2){
        u64 w0 = *(const u64*)&wo[f*64];
        u64 w1 = *(const u64*)&wo[(f+1)*64];
        #pragma unroll
        for (int j = 0; j < 4; j++){
            ulonglong2 x = *(const ulonglong2*)&xs[(ng*4+j)*64 + f];
            fma2(acc[j], x.x, w0); fma2(acc[j], x.y, w1);
        }
    }
    #pragma unroll
    for (int j = 0; j < 4; j++){
        int n = n0 + ng*4 + j;
        if (n < NN){
            float2 sc = g_sc2[n];
            float mc = sc.x / fmaxf(sc.y, 1.f);
            int idx = ((n*PP+p)*MM+m)*FF + g0;
            float2 o = u2f2(acc[j]);
            float2 xp = *(const float2*)&g_xpre[idx];
            if (mc < 1e-5f) o = xp;
            float2 a1 = *(const float2*)&g_c[(size_t)n*CDIM + OFF_A1 + (p*3+l)*64 + g0];
            float2 fv = *(const float2*)&fn[idx];
            *(float2*)&g_x1[idx] = make_float2(fv.x + a1.x*o.x, fv.y + a1.y*o.y);
        }
    }
}

// ---------------- gelu-ratio gate from h[:,0,0,:] ----------------
__global__ void k_gate(const float* __restrict__ W1){
    int n = blockIdx.x;
    __shared__ __align__(16) float xs[64];
    int tid = threadIdx.x; // 256
    if (tid < 64) xs[tid] = g_xpre2[(size_t)n*1152 + tid];
    __syncthreads();
    float acc = 0.f;
    for (int f = 0; f < 64; f += 4){
        float4 x = *(const float4*)&xs[f];
        acc += x.x*W1[f*256+tid] + x.y*W1[(f+1)*256+tid]
             + x.z*W1[(f+2)*256+tid] + x.w*W1[(f+3)*256+tid];
    }
    float s = acc;
    float t = tanhf(0.7978845608028654f*(s + 0.044715f*s*s*s));
    g_gate[(size_t)n*NF + tid] = 0.5f*(1.f + t);
}

// ---------------- fused MLP: 16 nodes/block, f32x2 both phases ----------------
__global__ void __launch_bounds__(256) k_mlp(const float* __restrict__ W1, const float* __restrict__ W2,
                      float* __restrict__ out){
    int n0 = blockIdx.x*16;
    int pm = blockIdx.y; int p = pm/9, m = pm - 9*p; int l = c_deg[m];
    __shared__ __align__(16) float2 xs[16*64];    // 8 KB dup
    __shared__ __align__(16) float2 hs[16*256];   // 32 KB dup
    int tid = threadIdx.x; // 256
    for (int i = tid; i < 1024; i += 256){
        int nn = i>>6, f = i&63; int n = n0+nn;
        float v = (n < NN) ? g_xpre2[((size_t)(n*PP+p)*MM+m)*FF + f] : 0.f;
        xs[i] = make_float2(v, v);
    }
    __syncthreads();
    // phase 1: h = (X @ W1) * gate
    {
        int jp = tid&127, ng = tid>>7;
        int j0 = 2*jp;
        const float* w1 = W1 + (size_t)(p*3+l)*64*256 + j0;
        u64 acc[8];
        #pragma unroll
        for (int nn = 0; nn < 8; nn++) acc[nn] = 0ull;
        for (int f = 0; f < 64; f += 2){
            u64 w0 = *(const u64*)&w1[f*256];
            u64 w1v = *(const u64*)&w1[(f+1)*256];
            #pragma unroll
            for (int nn = 0; nn < 8; nn++){
                ulonglong2 x = *(const ulonglong2*)&xs[(ng*8+nn)*64 + f];
                fma2(acc[nn], x.x, w0); fma2(acc[nn], x.y, w1v);
            }
        }
        #pragma unroll
        for (int nn = 0; nn < 8; nn++){
            int node = ng*8+nn;
            int n = n0 + node;
            float2 gt = (n < NN) ? *(const float2*)&g_gate[(size_t)n*NF + j0] : make_float2(0.f,0.f);
            float2 h = u2f2(acc[nn]);
            float h0 = h.x*gt.x, h1 = h.y*gt.y;
            hs[node*256 + j0]     = make_float2(h0, h0);
            hs[node*256 + j0 + 1] = make_float2(h1, h1);
        }
    }
    __syncthreads();
    // phase 2: out = gate(a2, h @ W2) + x1
    {
        int gp = tid&31, ng = tid>>5;
        int g0 = 2*gp;
        const float* w2 = W2 + (size_t)(p*3+l)*256*64 + g0;
        u64 acc[2] = {0ull, 0ull};
        for (int jj = 0; jj < 256; jj += 2){
            u64 w0 = *(const u64*)&w2[jj*64];
            u64 w1v = *(const u64*)&w2[(jj+1)*64];
            #pragma unroll
            for (int k2 = 0; k2 < 2; k2++){
                ulonglong2 h = *(const ulonglong2*)&hs[(ng*2+k2)*256 + jj];
                fma2(acc[k2], h.x, w0); fma2(acc[k2], h.y, w1v);
            }
        }
        #pragma unroll
        for (int k2 = 0; k2 < 2; k2++){
            int n = n0 + ng*2 + k2;
            if (n < NN){
                int idx = ((n*PP+p)*MM+m)*FF + g0;
                float2 a2 = *(const float2*)&g_c[(size_t)n*CDIM + OFF_A2 + (p*3+l)*64 + g0];
                float2 r = u2f2(acc[k2]);
                float2 x1 = *(const float2*)&g_x1[idx];
                *(float2*)&out[idx] = make_float2(x1.x + a2.x*r.x, x1.y + a2.y*r.y);
            }
        }
    }
}

extern "C" void kernel_launch(void* const* d_in, const int* in_sizes, int n_in,
                              void* d_out, int out_size){
    const float* fn    = (const float*)d_in[0];
    const float* fe    = (const float*)d_in[1];
    const float* ft    = (const float*)d_in[2];
    const float* cut   = (const float*)d_in[3];
    const float* lns   = (const float*)d_in[4];
    const float* lnb   = (const float*)d_in[5];
    const float* Wc    = (const float*)d_in[6];
    const float* bc    = (const float*)d_in[7];
    const float* Wq    = (const float*)d_in[8];
    const float* Wk    = (const float*)d_in[9];
    const float* Wv    = (const float*)d_in[10];
    const float* Wo    = (const float*)d_in[11];
    const float* Weqk  = (const float*)d_in[12];
    const float* Wev   = (const float*)d_in[13];
    const float* W1    = (const float*)d_in[14];
    const float* W2    = (const float*)d_in[15];
    const int*   src   = (const int*)d_in[16];
    const int*   dst   = (const int*)d_in[17];
    float* out = (float*)d_out;

    k_timecond<<<NN/8, 256>>>(ft, lns, lnb, Wc, bc);   // includes init
    k_ln_mod<0><<<NN, 192>>>(fn);
    dim3 gpm((NN+31)/32, PP*MM);
    k_qkv<<<gpm, 256>>>(Wq, Wk, Wv);
    k_logits<<<NE/4, 128>>>(fe, Weqk, src, dst);       // launch #4 -> profiled
    k_softmax_w<<<(NE+255)/256, 256>>>(dst, cut);
    k_scatter<<<NE/4, 128>>>(fe, Wev, src, dst);
    k_out_res<<<gpm, 256>>>(fn, Wo);
    k_ln_mod<1><<<NN, 192>>>(fn);
    k_gate<<<NN, 256>>>(W1);
    dim3 gpm16((NN+15)/16, PP*MM);
    k_mlp<<<gpm16, 256>>>(W1, W2, out);
}

// round 9
// speedup vs baseline: 1.0919x; 1.0599x over previous
#include <cuda_runtime.h>
#include <math.h>

#define NN 6000
#define NE 72000
#define PP 2
#define MM 9
#define FF 64
#define HH 4
#define CDIM 1664
#define NF 256
#define NPMF (NN*PP*MM*FF)

#define OFF_G1 0
#define OFF_B1 384
#define OFF_A1 448
#define OFF_G2 832
#define OFF_B2 1216
#define OFF_A2 1280

typedef unsigned long long u64;

__constant__ int c_deg[9] = {0,1,1,1,2,2,2,2,2};

// ---- scratch (static device globals; no runtime allocation) ----
__device__ float    g_c[NN*CDIM];
__device__ __align__(16) float g_xpre[NPMF];
__device__ __align__(16) float g_q[NPMF];
__device__ __align__(16) float g_k[NPMF];
__device__ __align__(16) float g_v[NPMF];
__device__ float    g_logits[NE*HH];
__device__ unsigned g_lmax[NN*HH];
__device__ float    g_w[NE*HH];
__device__ __align__(16) float g_denom[NN*HH];
__device__ __align__(8)  float2 g_sc2[NN];     // {sumcut, cnt}
__device__ __align__(16) float g_att[NPMF];
__device__ __align__(16) float g_x1[NPMF];
__device__ __align__(16) float g_xpre2[NPMF];
__device__ __align__(16) float g_gate[NN*NF];
// packed edge weights: [t][g] = (W[2t][g], W[2t+1][g]), t in [0,32), g in [0,64)
__device__ __align__(16) float2 g_eqkP[2048];
__device__ __align__(16) float2 g_evP[2048];

__device__ __forceinline__ void fma2(u64 &d, u64 a, u64 b){
    asm("fma.rn.f32x2 %0, %1, %2, %0;" : "+l"(d) : "l"(a), "l"(b));
}
__device__ __forceinline__ float2 u2f2(u64 a){
    return make_float2(__uint_as_float((unsigned)a), __uint_as_float((unsigned)(a>>32)));
}
__device__ __forceinline__ float hsum2(u64 a){
    return __uint_as_float((unsigned)a) + __uint_as_float((unsigned)(a>>32));
}
__device__ __forceinline__ u64 pk2(float a, float b){
    u64 r; asm("mov.b64 %0, {%1,%2};" : "=l"(r) : "f"(a), "f"(b)); return r;
}
__device__ __forceinline__ unsigned flipf(float f){
    unsigned u = __float_as_uint(f);
    return (u & 0x80000000u) ? ~u : (u | 0x80000000u);
}
__device__ __forceinline__ float unflipf(unsigned u){
    return __uint_as_float((u & 0x80000000u) ? (u ^ 0x80000000u) : ~u);
}

// ---------------- time conditioning (+ folded init + weight pack) ----------------
__global__ void k_timecond(const float* __restrict__ ft, const float* __restrict__ scale,
                           const float* __restrict__ bias, const float* __restrict__ Wc,
                           const float* __restrict__ bc, const float* __restrict__ Weqk,
                           const float* __restrict__ Wev){
    __shared__ __align__(16) float2 sd[8*64];   // duplicated activations
    int n0 = blockIdx.x*8;
    int tid = threadIdx.x; // 256
    int gid = blockIdx.x*256 + tid;
    // folded init + edge-weight pack
    {
        float4 z = make_float4(0.f,0.f,0.f,0.f);
        for (int i = gid; i < NPMF/4; i += 750*256) ((float4*)g_att)[i] = z;
        if (gid < NN*HH){ g_denom[gid] = 0.f; g_lmax[gid] = 0u; }
        if (gid < NN) g_sc2[gid] = make_float2(0.f, 0.f);
        if (gid < 4096){
            int wsel = gid >> 11;
            int idx = gid & 2047;
            int t = idx >> 6, g = idx & 63;
            const float* W = wsel ? Wev : Weqk;
            float2 v = make_float2(W[(2*t)*64+g], W[(2*t+1)*64+g]);
            (wsel ? g_evP : g_eqkP)[idx] = v;
        }
    }
    __shared__ __align__(16) float s[8][64];
    for (int i = tid; i < 512; i += 256){
        int nn = i>>6, f = i&63; int n = n0+nn;
        s[nn][f] = (n < NN) ? ft[n*64+f] : 0.f;
    }
    __syncthreads();
    int w = tid>>5, lane = tid&31;
    {
        float v0 = s[w][lane], v1 = s[w][lane+32];
        float sum = v0+v1, sq = v0*v0 + v1*v1;
        #pragma unroll
        for (int o = 16; o; o >>= 1){
            sum += __shfl_xor_sync(0xffffffffu, sum, o);
            sq  += __shfl_xor_sync(0xffffffffu, sq , o);
        }
        float mu = sum*(1.f/64.f);
        float var = sq*(1.f/64.f) - mu*mu;
        float rstd = rsqrtf(var + 1e-6f);
        float c0 = (v0-mu)*rstd*scale[lane]    + bias[lane];
        float c1 = (v1-mu)*rstd*scale[lane+32] + bias[lane+32];
        float y0 = c0 / (1.f + __expf(-c0));
        float y1 = c1 / (1.f + __expf(-c1));
        sd[w*64 + lane]      = make_float2(y0, y0);
        sd[w*64 + lane + 32] = make_float2(y1, y1);
    }
    __syncthreads();
    for (int jp = tid; jp < CDIM/2; jp += 256){
        int j0 = 2*jp;
        u64 acc[8];
        #pragma unroll
        for (int nn = 0; nn < 8; nn++) acc[nn] = 0ull;
        for (int t = 0; t < 64; t += 2){
            u64 w0 = *(const u64*)&Wc[(size_t)t*CDIM + j0];
            u64 w1 = *(const u64*)&Wc[(size_t)(t+1)*CDIM + j0];
            #pragma unroll
            for (int nn = 0; nn < 8; nn++){
                ulonglong2 x = *(const ulonglong2*)&sd[nn*64 + t];
                fma2(acc[nn], x.x, w0);
                fma2(acc[nn], x.y, w1);
            }
        }
        float2 bb = *(const float2*)&bc[j0];
        #pragma unroll
        for (int nn = 0; nn < 8; nn++){
            int n = n0+nn;
            if (n < NN){
                float2 r = u2f2(acc[nn]);
                *(float2*)&g_c[(size_t)n*CDIM + j0] = make_float2(r.x + bb.x, r.y + bb.y);
            }
        }
    }
}

// ---------------- equivariant LN + modulate ----------------
template<int PASS>
__global__ void k_ln_mod(const float* __restrict__ fn){
    int n = blockIdx.x;
    const float* xin  = PASS ? g_x1 : fn;
    float*       xout = PASS ? g_xpre2 : g_xpre;
    const int offG = PASS ? OFF_G2 : OFF_G1;
    const int offB = PASS ? OFF_B2 : OFF_B1;
    __shared__ float sm[1152];
    __shared__ float s_inv[2][3];
    __shared__ float s_mean[2];
    int tid = threadIdx.x; // 192
    for (int i = tid; i < 1152; i += 192) sm[i] = xin[(size_t)n*1152 + i];
    __syncthreads();
    int w = tid>>5, lane = tid&31;   // 6 warps = (p,l) pairs
    int p = w/3, l = w - 3*p;
    int base = p*576 + l*l*64;
    int cnt = (2*l+1)*64;
    float ss = 0.f, s1 = 0.f;
    for (int i = lane; i < cnt; i += 32){ float v = sm[base+i]; ss += v*v; s1 += v; }
    #pragma unroll
    for (int o = 16; o; o >>= 1){
        ss += __shfl_xor_sync(0xffffffffu, ss, o);
        s1 += __shfl_xor_sync(0xffffffffu, s1, o);
    }
    if (lane == 0){
        if (l == 0){ float mean = s1*(1.f/64.f); s_mean[p] = mean; ss -= 64.f*mean*mean; }
        s_inv[p][l] = rsqrtf(ss/(float)cnt + 1e-6f);
    }
    __syncthreads();
    const float* cc = g_c + (size_t)n*CDIM;
    for (int i = tid; i < 1152; i += 192){
        int p2 = i/576; int r = i - 576*p2; int m = r>>6; int f = r&63;
        int l2 = c_deg[m];
        float v = sm[i];
        if (m == 0) v -= s_mean[p2];
        float gmod = cc[offG + (p2*3+l2)*64 + f];
        float y = v * s_inv[p2][l2] * (1.f + gmod);
        if (m == 0) y += cc[offB + f];
        xout[(size_t)n*1152 + i] = y;
    }
}

// ---------------- QKV projections: 32 nodes/block, g-pair f32x2 ----------------
__global__ void __launch_bounds__(256) k_qkv(const float* __restrict__ Wq, const float* __restrict__ Wk,
                      const float* __restrict__ Wv){
    int n0 = blockIdx.x*32;
    int pm = blockIdx.y; int p = pm/9, m = pm - 9*p; int l = c_deg[m];
    __shared__ __align__(16) float2 xs[32*64];   // duplicated, 16 KB
    int tid = threadIdx.x; // 256
    for (int i = tid; i < 2048; i += 256){
        int nn = i>>6, f = i&63; int n = n0+nn;
        float v = (n < NN) ? g_xpre[((size_t)(n*PP+p)*MM+m)*FF + f] : 0.f;
        xs[i] = make_float2(v, v);
    }
    __syncthreads();
    int gp = tid&31, ng = tid>>5;   // 32 g-pairs x 8 node-groups(4 nodes)
    int g0 = 2*gp;
    const float* wq = Wq + (size_t)(p*3+l)*4096 + g0;
    const float* wk = Wk + (size_t)(p*3+l)*4096 + g0;
    const float* wv = Wv + (size_t)(p*3+l)*4096 + g0;
    u64 aq[4], ak[4], av[4];
    #pragma unroll
    for (int j = 0; j < 4; j++){ aq[j]=0ull; ak[j]=0ull; av[j]=0ull; }
    for (int f = 0; f < 64; f += 2){
        u64 q0 = *(const u64*)&wq[f*64],     k0 = *(const u64*)&wk[f*64],     v0 = *(const u64*)&wv[f*64];
        u64 q1 = *(const u64*)&wq[(f+1)*64], k1 = *(const u64*)&wk[(f+1)*64], v1 = *(const u64*)&wv[(f+1)*64];
        #pragma unroll
        for (int j = 0; j < 4; j++){
            ulonglong2 x = *(const ulonglong2*)&xs[(ng*4+j)*64 + f];
            fma2(aq[j], x.x, q0); fma2(aq[j], x.y, q1);
            fma2(ak[j], x.x, k0); fma2(ak[j], x.y, k1);
            fma2(av[j], x.x, v0); fma2(av[j], x.y, v1);
        }
    }
    #pragma unroll
    for (int j = 0; j < 4; j++){
        int n = n0 + ng*4 + j;
        if (n < NN){
            int idx = ((n*PP+p)*MM+m)*FF + g0;
            *(float2*)&g_q[idx] = u2f2(aq[j]);
            *(float2*)&g_k[idx] = u2f2(ak[j]);
            *(float2*)&g_v[idx] = u2f2(av[j]);
        }
    }
}

// ---------------- per-edge: e_qk projection (f-paired) + logits + segment max ----------------
__global__ void __launch_bounds__(128) k_logits(const float* __restrict__ fe,
                         const int* __restrict__ src, const int* __restrict__ dst){
    int e0 = blockIdx.x*4;
    __shared__ __align__(16) float sfe[4*576];    // 9 KB, plain
    __shared__ __align__(16) float seqk[4*576];   // 9 KB
    int tid = threadIdx.x; // 128
    const float4* fp = (const float4*)(fe + (size_t)e0*576);
    for (int i = tid; i < 576; i += 128) ((float4*)sfe)[i] = fp[i];
    __syncthreads();
    // projection: warp = edge, lane owns g0=2*lane, g0+1; accumulate f32x2 over (even f, odd f)
    {
        int e = tid>>5, lane = tid&31;
        int g0 = 2*lane;
        const float4* wp = (const float4*)g_eqkP;   // [t][g] float2 -> float4 index t*32+lane
        const float* xb = sfe + e*576;
        u64 accA[9], accB[9];
        #pragma unroll
        for (int m = 0; m < 9; m++){ accA[m]=0ull; accB[m]=0ull; }
        #pragma unroll 8
        for (int t = 0; t < 32; t++){
            float4 wv = wp[t*32 + lane];
            u64 wA = pk2(wv.x, wv.y);   // (W[2t,g0], W[2t+1,g0])
            u64 wB = pk2(wv.z, wv.w);   // (W[2t,g0+1], W[2t+1,g0+1])
            #pragma unroll
            for (int m = 0; m < 9; m++){
                u64 xx = *(const u64*)&xb[m*64 + 2*t];   // warp-uniform broadcast
                fma2(accA[m], xx, wA);
                fma2(accB[m], xx, wB);
            }
        }
        #pragma unroll
        for (int m = 0; m < 9; m++)
            *(float2*)&seqk[e*576 + m*64 + g0] = make_float2(hsum2(accA[m]), hsum2(accB[m]));
    }
    __syncthreads();
    // dot phase: warp = edge, lane = (h, i) ; 2 f per lane per pm step
    {
        int we = tid>>5, lane = tid&31;
        int h = lane>>3, i = lane&7;
        int s = src[e0+we], d = dst[e0+we];
        int f0 = h*16 + 2*i;
        const float* qb = g_q + (size_t)d*1152 + f0;
        const float* kb = g_k + (size_t)s*1152 + f0;
        const float* sb = seqk + we*576 + f0;
        float acc = 0.f;
        #pragma unroll
        for (int pm = 0; pm < 18; pm++){
            int moff = (pm >= 9 ? pm-9 : pm)*64;
            float2 q2 = *(const float2*)&qb[pm*64];
            float2 k2 = *(const float2*)&kb[pm*64];
            float2 s2 = *(const float2*)&sb[moff];
            acc += q2.x*k2.x*s2.x + q2.y*k2.y*s2.y;
        }
        acc += __shfl_xor_sync(0xffffffffu, acc, 1);
        acc += __shfl_xor_sync(0xffffffffu, acc, 2);
        acc += __shfl_xor_sync(0xffffffffu, acc, 4);
        if (i == 0){
            float lg = acc * 0.05892556509887896f;  // 1/sqrt(288)
            g_logits[(e0+we)*HH + h] = lg;
            atomicMax(&g_lmax[d*HH + h], flipf(lg));
        }
    }
}

// ---------------- softmax weights + segment sums (vectorized reds) ----------------
__global__ void k_softmax_w(const int* __restrict__ dst, const float* __restrict__ cutoff){
    int e = blockIdx.x*256 + threadIdx.x;
    if (e >= NE) return;
    int d = dst[e];
    float cut = cutoff[e];
    float wv[HH];
    #pragma unroll
    for (int h = 0; h < HH; h++){
        float lg = g_logits[e*HH + h];
        float lm = unflipf(g_lmax[d*HH + h]);
        wv[h] = __expf(lg - lm) * cut;
        g_w[e*HH + h] = wv[h];
    }
    asm volatile("red.global.add.v4.f32 [%0], {%1,%2,%3,%4};"
                 :: "l"(&g_denom[d*HH]), "f"(wv[0]), "f"(wv[1]), "f"(wv[2]), "f"(wv[3])
                 : "memory");
    asm volatile("red.global.add.v2.f32 [%0], {%1,%2};"
                 :: "l"(&g_sc2[d]), "f"(cut), "f"(1.0f) : "memory");
}

// ---------------- per-edge: e_v projection (f-paired) + attn*v scatter ----------------
__global__ void __launch_bounds__(128) k_scatter(const float* __restrict__ fe,
                          const int* __restrict__ src, const int* __restrict__ dst){
    int e0 = blockIdx.x*4;
    __shared__ __align__(16) float sfe[4*576];    // 9 KB
    __shared__ __align__(16) float sev[4*576];    // 9 KB
    __shared__ float satt[4][4];
    int tid = threadIdx.x; // 128
    const float4* fp = (const float4*)(fe + (size_t)e0*576);
    for (int i = tid; i < 576; i += 128) ((float4*)sfe)[i] = fp[i];
    if (tid < 16){
        int e = tid>>2, h = tid&3;
        int d = dst[e0+e];
        satt[e][h] = g_w[(e0+e)*HH + h] / (g_denom[d*HH + h] + 1e-9f);
    }
    __syncthreads();
    {
        int e = tid>>5, lane = tid&31;
        int g0 = 2*lane;
        const float4* wp = (const float4*)g_evP;
        const float* xb = sfe + e*576;
        u64 accA[9], accB[9];
        #pragma unroll
        for (int m = 0; m < 9; m++){ accA[m]=0ull; accB[m]=0ull; }
        #pragma unroll 8
        for (int t = 0; t < 32; t++){
            float4 wv = wp[t*32 + lane];
            u64 wA = pk2(wv.x, wv.y);
            u64 wB = pk2(wv.z, wv.w);
            #pragma unroll
            for (int m = 0; m < 9; m++){
                u64 xx = *(const u64*)&xb[m*64 + 2*t];
                fma2(accA[m], xx, wA);
                fma2(accB[m], xx, wB);
            }
        }
        #pragma unroll
        for (int m = 0; m < 9; m++)
            *(float2*)&sev[e*576 + m*64 + g0] = make_float2(hsum2(accA[m]), hsum2(accB[m]));
    }
    __syncthreads();
    #pragma unroll
    for (int e = 0; e < 4; e++){
        int d = dst[e0+e], s = src[e0+e];
        for (int i4 = tid; i4 < 288; i4 += 128){
            int i = i4*4;
            int p = i/576; int r = i - 576*p; int m = r>>6; int f = r&63; int h = f>>4;
            float4 vv = *(const float4*)&g_v[((size_t)(s*PP+p)*MM+m)*FF + f];
            float4 ev = *(const float4*)&sev[e*576 + m*64+f];
            float a = satt[e][h];
            float* op = &g_att[((size_t)(d*PP+p)*MM+m)*FF + f];
            float r0 = a*vv.x*ev.x, r1 = a*vv.y*ev.y, r2 = a*vv.z*ev.z, r3 = a*vv.w*ev.w;
            asm volatile("red.global.add.v4.f32 [%0], {%1,%2,%3,%4};"
                         :: "l"(op), "f"(r0), "f"(r1), "f"(r2), "f"(r3) : "memory");
        }
    }
}

// ---------------- Wo projection + mean_cut select + residual 1 (32 nodes/block, f32x2) ----------------
__global__ void __launch_bounds__(256) k_out_res(const float* __restrict__ fn, const float* __restrict__ Wo){
    int n0 = blockIdx.x*32;
    int pm = blockIdx.y; int p = pm/9, m = pm - 9*p; int l = c_deg[m];
    __shared__ __align__(16) float2 xs[32*64];   // 16 KB
    int tid = threadIdx.x; // 256
    for (int i = tid; i < 2048; i += 256){
        int nn = i>>6, f = i&63; int n = n0+nn;
        float v = (n < NN) ? g_att[((size_t)(n*PP+p)*MM+m)*FF + f] : 0.f;
        xs[i] = make_float2(v, v);
    }
    __syncthreads();
    int gp = tid&31, ng = tid>>5;
    int g0 = 2*gp;
    const float* wo = Wo + (size_t)(p*3+l)*4096 + g0;
    u64 acc[4];
    #pragma unroll
    for (int j = 0; j < 4; j++) acc[j] = 0ull;
    for (int f = 0; f < 64; f += 2){
        u64 w0 = *(const u64*)&wo[f*64];
        u64 w1 = *(const u64*)&wo[(f+1)*64];
        #pragma unroll
        for (int j = 0; j < 4; j++){
            ulonglong2 x = *(const ulonglong2*)&xs[(ng*4+j)*64 + f];
            fma2(acc[j], x.x, w0); fma2(acc[j], x.y, w1);
        }
    }
    #pragma unroll
    for (int j = 0; j < 4; j++){
        int n = n0 + ng*4 + j;
        if (n < NN){
            float2 sc = g_sc2[n];
            float mc = sc.x / fmaxf(sc.y, 1.f);
            int idx = ((n*PP+p)*MM+m)*FF + g0;
            float2 o = u2f2(acc[j]);
            float2 xp = *(const float2*)&g_xpre[idx];
            if (mc < 1e-5f) o = xp;
            float2 a1 = *(const float2*)&g_c[(size_t)n*CDIM + OFF_A1 + (p*3+l)*64 + g0];
            float2 fv = *(const float2*)&fn[idx];
            *(float2*)&g_x1[idx] = make_float2(fv.x + a1.x*o.x, fv.y + a1.y*o.y);
        }
    }
}

// ---------------- gelu-ratio gate from h[:,0,0,:] ----------------
__global__ void k_gate(const float* __restrict__ W1){
    int n = blockIdx.x;
    __shared__ __align__(16) float xs[64];
    int tid = threadIdx.x; // 256
    if (tid < 64) xs[tid] = g_xpre2[(size_t)n*1152 + tid];
    __syncthreads();
    float acc = 0.f;
    for (int f = 0; f < 64; f += 4){
        float4 x = *(const float4*)&xs[f];
        acc += x.x*W1[f*256+tid] + x.y*W1[(f+1)*256+tid]
             + x.z*W1[(f+2)*256+tid] + x.w*W1[(f+3)*256+tid];
    }
    float s = acc;
    float t = tanhf(0.7978845608028654f*(s + 0.044715f*s*s*s));
    g_gate[(size_t)n*NF + tid] = 0.5f*(1.f + t);
}

// ---------------- fused MLP: 16 nodes/block, f32x2 both phases ----------------
__global__ void __launch_bounds__(256) k_mlp(const float* __restrict__ W1, const float* __restrict__ W2,
                      float* __restrict__ out){
    int n0 = blockIdx.x*16;
    int pm = blockIdx.y; int p = pm/9, m = pm - 9*p; int l = c_deg[m];
    __shared__ __align__(16) float2 xs[16*64];    // 8 KB dup
    __shared__ __align__(16) float2 hs[16*256];   // 32 KB dup
    int tid = threadIdx.x; // 256
    for (int i = tid; i < 1024; i += 256){
        int nn = i>>6, f = i&63; int n = n0+nn;
        float v = (n < NN) ? g_xpre2[((size_t)(n*PP+p)*MM+m)*FF + f] : 0.f;
        xs[i] = make_float2(v, v);
    }
    __syncthreads();
    // phase 1: h = (X @ W1) * gate
    {
        int jp = tid&127, ng = tid>>7;
        int j0 = 2*jp;
        const float* w1 = W1 + (size_t)(p*3+l)*64*256 + j0;
        u64 acc[8];
        #pragma unroll
        for (int nn = 0; nn < 8; nn++) acc[nn] = 0ull;
        for (int f = 0; f < 64; f += 2){
            u64 w0 = *(const u64*)&w1[f*256];
            u64 w1v = *(const u64*)&w1[(f+1)*256];
            #pragma unroll
            for (int nn = 0; nn < 8; nn++){
                ulonglong2 x = *(const ulonglong2*)&xs[(ng*8+nn)*64 + f];
                fma2(acc[nn], x.x, w0); fma2(acc[nn], x.y, w1v);
            }
        }
        #pragma unroll
        for (int nn = 0; nn < 8; nn++){
            int node = ng*8+nn;
            int n = n0 + node;
            float2 gt = (n < NN) ? *(const float2*)&g_gate[(size_t)n*NF + j0] : make_float2(0.f,0.f);
            float2 h = u2f2(acc[nn]);
            float h0 = h.x*gt.x, h1 = h.y*gt.y;
            hs[node*256 + j0]     = make_float2(h0, h0);
            hs[node*256 + j0 + 1] = make_float2(h1, h1);
        }
    }
    __syncthreads();
    // phase 2: out = gate(a2, h @ W2) + x1
    {
        int gp = tid&31, ng = tid>>5;
        int g0 = 2*gp;
        const float* w2 = W2 + (size_t)(p*3+l)*256*64 + g0;
        u64 acc[2] = {0ull, 0ull};
        for (int jj = 0; jj < 256; jj += 2){
            u64 w0 = *(const u64*)&w2[jj*64];
            u64 w1v = *(const u64*)&w2[(jj+1)*64];
            #pragma unroll
            for (int k2 = 0; k2 < 2; k2++){
                ulonglong2 h = *(const ulonglong2*)&hs[(ng*2+k2)*256 + jj];
                fma2(acc[k2], h.x, w0); fma2(acc[k2], h.y, w1v);
            }
        }
        #pragma unroll
        for (int k2 = 0; k2 < 2; k2++){
            int n = n0 + ng*2 + k2;
            if (n < NN){
                int idx = ((n*PP+p)*MM+m)*FF + g0;
                float2 a2 = *(const float2*)&g_c[(size_t)n*CDIM + OFF_A2 + (p*3+l)*64 + g0];
                float2 r = u2f2(acc[k2]);
                float2 x1 = *(const float2*)&g_x1[idx];
                *(float2*)&out[idx] = make_float2(x1.x + a2.x*r.x, x1.y + a2.y*r.y);
            }
        }
    }
}

extern "C" void kernel_launch(void* const* d_in, const int* in_sizes, int n_in,
                              void* d_out, int out_size){
    const float* fn    = (const float*)d_in[0];
    const float* fe    = (const float*)d_in[1];
    const float* ft    = (const float*)d_in[2];
    const float* cut   = (const float*)d_in[3];
    const float* lns   = (const float*)d_in[4];
    const float* lnb   = (const float*)d_in[5];
    const float* Wc    = (const float*)d_in[6];
    const float* bc    = (const float*)d_in[7];
    const float* Wq    = (const float*)d_in[8];
    const float* Wk    = (const float*)d_in[9];
    const float* Wv    = (const float*)d_in[10];
    const float* Wo    = (const float*)d_in[11];
    const float* Weqk  = (const float*)d_in[12];
    const float* Wev   = (const float*)d_in[13];
    const float* W1    = (const float*)d_in[14];
    const float* W2    = (const float*)d_in[15];
    const int*   src   = (const int*)d_in[16];
    const int*   dst   = (const int*)d_in[17];
    float* out = (float*)d_out;

    k_timecond<<<NN/8, 256>>>(ft, lns, lnb, Wc, bc, Weqk, Wev);   // init + weight pack
    k_ln_mod<0><<<NN, 192>>>(fn);
    dim3 gpm((NN+31)/32, PP*MM);
    k_qkv<<<gpm, 256>>>(Wq, Wk, Wv);
    k_logits<<<NE/4, 128>>>(fe, src, dst);       // profiled launch
    k_softmax_w<<<(NE+255)/256, 256>>>(dst, cut);
    k_scatter<<<NE/4, 128>>>(fe, src, dst);
    k_out_res<<<gpm, 256>>>(fn, Wo);
    k_ln_mod<1><<<NN, 192>>>(fn);
    k_gate<<<NN, 256>>>(W1);
    dim3 gpm16((NN+15)/16, PP*MM);
    k_mlp<<<gpm16, 256>>>(W1, W2, out);
}